// round 2
// baseline (speedup 1.0000x reference)
#include <cuda_runtime.h>
#include <math.h>

#define S_LEN  2048
#define D_MODEL 1024
#define NHEAD  16
#define HDIM   64

// Scratch (device globals: allocation-free, zero-initialized at module load).
// g_qk upper triangle is NEVER written -> stays zero across graph replays (deterministic).
static __device__ float g_q[S_LEN * D_MODEL];
static __device__ float g_k[S_LEN * D_MODEL];
static __device__ float g_v[S_LEN * D_MODEL];
static __device__ float g_qk[(size_t)NHEAD * S_LEN * S_LEN];
static __device__ float g_L[NHEAD * S_LEN];
static __device__ float g_c[NHEAD * HDIM];
static __device__ float g_z[S_LEN * D_MODEL];

// ---------------------------------------------------------------------------
// NT GEMM with bias: C[M,N] = A[M,K] * B[N,K]^T + bias[N]
// 128x128 tile, BK=8, 256 threads, 8x8 per thread.
// Requires M%128==0, N%128==0, K%8==0.
// ---------------------------------------------------------------------------
__global__ __launch_bounds__(256)
void sgemm_nt_bias(const float* __restrict__ A, const float* __restrict__ B,
                   const float* __restrict__ bias, float* __restrict__ C,
                   int K, int lda, int ldb, int ldc)
{
    __shared__ float As[8][128];
    __shared__ float Bs[8][128];
    const int tid  = threadIdx.x;
    const int tx   = tid & 15;
    const int ty   = tid >> 4;
    const int row0 = blockIdx.y << 7;
    const int col0 = blockIdx.x << 7;
    const int lrow = tid >> 1;
    const int lk   = (tid & 1) << 2;

    const float* Ap = A + (size_t)(row0 + lrow) * lda + lk;
    const float* Bp = B + (size_t)(col0 + lrow) * ldb + lk;

    float acc[8][8];
#pragma unroll
    for (int i = 0; i < 8; i++)
#pragma unroll
        for (int j = 0; j < 8; j++) acc[i][j] = 0.f;

    for (int k0 = 0; k0 < K; k0 += 8) {
        float4 av = *(const float4*)(Ap + k0);
        float4 bv = *(const float4*)(Bp + k0);
        As[lk + 0][lrow] = av.x; As[lk + 1][lrow] = av.y;
        As[lk + 2][lrow] = av.z; As[lk + 3][lrow] = av.w;
        Bs[lk + 0][lrow] = bv.x; Bs[lk + 1][lrow] = bv.y;
        Bs[lk + 2][lrow] = bv.z; Bs[lk + 3][lrow] = bv.w;
        __syncthreads();
#pragma unroll
        for (int kk = 0; kk < 8; kk++) {
            float a[8], b[8];
            *(float4*)&a[0] = *(const float4*)&As[kk][(ty << 3)];
            *(float4*)&a[4] = *(const float4*)&As[kk][(ty << 3) + 4];
            *(float4*)&b[0] = *(const float4*)&Bs[kk][(tx << 3)];
            *(float4*)&b[4] = *(const float4*)&Bs[kk][(tx << 3) + 4];
#pragma unroll
            for (int i = 0; i < 8; i++)
#pragma unroll
                for (int j = 0; j < 8; j++)
                    acc[i][j] = fmaf(a[i], b[j], acc[i][j]);
        }
        __syncthreads();
    }

    float bb[8];
    *(float4*)&bb[0] = *(const float4*)&bias[col0 + (tx << 3)];
    *(float4*)&bb[4] = *(const float4*)&bias[col0 + (tx << 3) + 4];
#pragma unroll
    for (int i = 0; i < 8; i++) {
        float* Cp = C + (size_t)(row0 + (ty << 3) + i) * ldc + col0 + (tx << 3);
        float4 o0 = make_float4(acc[i][0] + bb[0], acc[i][1] + bb[1],
                                acc[i][2] + bb[2], acc[i][3] + bb[3]);
        float4 o1 = make_float4(acc[i][4] + bb[4], acc[i][5] + bb[5],
                                acc[i][6] + bb[6], acc[i][7] + bb[7]);
        *(float4*)&Cp[0] = o0;
        *(float4*)&Cp[4] = o1;
    }
}

// ---------------------------------------------------------------------------
// Per-head masked QK^T: qk[h][s][t] = (t<=s) ? q[h,s,:].k[h,t,:] : 0
// Only tiles intersecting the lower triangle are launched (bx<=by); the rest
// of g_qk stays zero (static init, never written).
// ---------------------------------------------------------------------------
__global__ __launch_bounds__(256)
void sgemm_qk()
{
    if (blockIdx.x > blockIdx.y) return;   // tile fully above diagonal
    const int h = blockIdx.z;
    const float* A = g_q + h * HDIM;                       // lda = D_MODEL
    const float* B = g_k + h * HDIM;                       // ldb = D_MODEL
    float* C = g_qk + (size_t)h * S_LEN * S_LEN;           // ldc = S_LEN

    __shared__ float As[8][128];
    __shared__ float Bs[8][128];
    const int tid  = threadIdx.x;
    const int tx   = tid & 15;
    const int ty   = tid >> 4;
    const int row0 = blockIdx.y << 7;   // s
    const int col0 = blockIdx.x << 7;   // t
    const int lrow = tid >> 1;
    const int lk   = (tid & 1) << 2;

    const float* Ap = A + (size_t)(row0 + lrow) * D_MODEL + lk;
    const float* Bp = B + (size_t)(col0 + lrow) * D_MODEL + lk;

    float acc[8][8];
#pragma unroll
    for (int i = 0; i < 8; i++)
#pragma unroll
        for (int j = 0; j < 8; j++) acc[i][j] = 0.f;

    for (int k0 = 0; k0 < HDIM; k0 += 8) {
        float4 av = *(const float4*)(Ap + k0);
        float4 bv = *(const float4*)(Bp + k0);
        As[lk + 0][lrow] = av.x; As[lk + 1][lrow] = av.y;
        As[lk + 2][lrow] = av.z; As[lk + 3][lrow] = av.w;
        Bs[lk + 0][lrow] = bv.x; Bs[lk + 1][lrow] = bv.y;
        Bs[lk + 2][lrow] = bv.z; Bs[lk + 3][lrow] = bv.w;
        __syncthreads();
#pragma unroll
        for (int kk = 0; kk < 8; kk++) {
            float a[8], b[8];
            *(float4*)&a[0] = *(const float4*)&As[kk][(ty << 3)];
            *(float4*)&a[4] = *(const float4*)&As[kk][(ty << 3) + 4];
            *(float4*)&b[0] = *(const float4*)&Bs[kk][(tx << 3)];
            *(float4*)&b[4] = *(const float4*)&Bs[kk][(tx << 3) + 4];
#pragma unroll
            for (int i = 0; i < 8; i++)
#pragma unroll
                for (int j = 0; j < 8; j++)
                    acc[i][j] = fmaf(a[i], b[j], acc[i][j]);
        }
        __syncthreads();
    }

#pragma unroll
    for (int i = 0; i < 8; i++) {
        const int r = row0 + (ty << 3) + i;
        float* Cp = C + (size_t)r * S_LEN + col0 + (tx << 3);
        float o[8];
#pragma unroll
        for (int j = 0; j < 8; j++) {
            const int cc = col0 + (tx << 3) + j;
            o[j] = (cc <= r) ? acc[i][j] : 0.f;
        }
        *(float4*)&Cp[0] = make_float4(o[0], o[1], o[2], o[3]);
        *(float4*)&Cp[4] = make_float4(o[4], o[5], o[6], o[7]);
    }
}

// ---------------------------------------------------------------------------
// Column logsumexp: L[h][t] = log( t * exp(0) + sum_{s>=t} exp(qk[h][s][t]/8) )
// Rows s < blockStart are all masked for every column in this block ->
// contribute exactly (float)blockStart; rows in [blockStart, t) read stored
// zeros so exp(0)=1 falls out naturally.
// ---------------------------------------------------------------------------
__global__ __launch_bounds__(256)
void col_lse_kernel()
{
    const int h  = blockIdx.y;
    const int t  = (blockIdx.x << 8) + threadIdx.x;
    const int s0 = blockIdx.x << 8;
    const float* base = g_qk + (size_t)h * S_LEN * S_LEN + t;

    float a0 = 0.f, a1 = 0.f, a2 = 0.f, a3 = 0.f;
    for (int s = s0; s < S_LEN; s += 4) {
        float v0 = base[(size_t)(s + 0) * S_LEN];
        float v1 = base[(size_t)(s + 1) * S_LEN];
        float v2 = base[(size_t)(s + 2) * S_LEN];
        float v3 = base[(size_t)(s + 3) * S_LEN];
        a0 += expf(v0 * 0.125f);
        a1 += expf(v1 * 0.125f);
        a2 += expf(v2 * 0.125f);
        a3 += expf(v3 * 0.125f);
    }
    g_L[h * S_LEN + t] = logf((float)s0 + ((a0 + a1) + (a2 + a3)));
}

// ---------------------------------------------------------------------------
// c[h][v] = sum_t L[h][t] * v[h][t][v]
// ---------------------------------------------------------------------------
__global__ __launch_bounds__(256)
void compute_c_kernel()
{
    __shared__ float part[4][HDIM];
    const int h = blockIdx.x;
    const int v = threadIdx.x & 63;
    const int g = threadIdx.x >> 6;   // 0..3
    const float* Lh = g_L + h * S_LEN;
    const float* vb = g_v + h * HDIM + v;
    float sum = 0.f;
    const int t0 = g * (S_LEN / 4);
    for (int t = t0; t < t0 + S_LEN / 4; t++)
        sum = fmaf(Lh[t], vb[(size_t)t * D_MODEL], sum);
    part[g][v] = sum;
    __syncthreads();
    if (g == 0)
        g_c[h * HDIM + v] = (part[0][v] + part[1][v]) + (part[2][v] + part[3][v]);
}

// ---------------------------------------------------------------------------
// Per-head attn: Z[s, h*64+v] = 0.125 * sum_{t<=s} qk[h][s][t]*v[h][t][v] - c[h][v]
// NN GEMM (B is [t][v], v contiguous). K-loop bounded at the diagonal block end.
// BM=128, BN=64, BK=8, 256 threads, 8x4 per thread.
// ---------------------------------------------------------------------------
__global__ __launch_bounds__(256)
void sgemm_attn()
{
    const int h    = blockIdx.y;
    const int row0 = blockIdx.x << 7;
    const float* A = g_qk + (size_t)h * S_LEN * S_LEN;  // lda = S_LEN
    const float* B = g_v + h * HDIM;                    // ldb = D_MODEL (NN)

    __shared__ float As[8][128];
    __shared__ float Bs[8][HDIM];
    const int tid  = threadIdx.x;
    const int tx   = tid & 15;          // 16 col groups * 4 = 64
    const int ty   = tid >> 4;          // 16 row groups * 8 = 128
    const int lrow = tid >> 1;
    const int lk   = (tid & 1) << 2;
    const int brow = tid >> 5;          // 0..7
    const int bcol = (tid & 31) << 1;   // 0..62

    float acc[8][4];
#pragma unroll
    for (int i = 0; i < 8; i++)
#pragma unroll
        for (int j = 0; j < 4; j++) acc[i][j] = 0.f;

    const int Kend = row0 + 128;        // only t <= s needed (zeros above diag)
    for (int k0 = 0; k0 < Kend; k0 += 8) {
        float4 av = *(const float4*)&A[(size_t)(row0 + lrow) * S_LEN + k0 + lk];
        float2 bv = *(const float2*)&B[(size_t)(k0 + brow) * D_MODEL + bcol];
        As[lk + 0][lrow] = av.x; As[lk + 1][lrow] = av.y;
        As[lk + 2][lrow] = av.z; As[lk + 3][lrow] = av.w;
        *(float2*)&Bs[brow][bcol] = bv;
        __syncthreads();
#pragma unroll
        for (int kk = 0; kk < 8; kk++) {
            float a[8], b[4];
            *(float4*)&a[0] = *(const float4*)&As[kk][(ty << 3)];
            *(float4*)&a[4] = *(const float4*)&As[kk][(ty << 3) + 4];
            *(float4*)&b[0] = *(const float4*)&Bs[kk][(tx << 2)];
#pragma unroll
            for (int i = 0; i < 8; i++)
#pragma unroll
                for (int j = 0; j < 4; j++)
                    acc[i][j] = fmaf(a[i], b[j], acc[i][j]);
        }
        __syncthreads();
    }

    float cv[4];
    *(float4*)&cv[0] = *(const float4*)&g_c[h * HDIM + (tx << 2)];
#pragma unroll
    for (int i = 0; i < 8; i++) {
        float* Cp = g_z + (size_t)(row0 + (ty << 3) + i) * D_MODEL + h * HDIM + (tx << 2);
        *(float4*)Cp = make_float4(acc[i][0] * 0.125f - cv[0],
                                   acc[i][1] * 0.125f - cv[1],
                                   acc[i][2] * 0.125f - cv[2],
                                   acc[i][3] * 0.125f - cv[3]);
    }
}

// ---------------------------------------------------------------------------
extern "C" void kernel_launch(void* const* d_in, const int* in_sizes, int n_in,
                              void* d_out, int out_size)
{
    const float* Qin = (const float*)d_in[0];
    const float* Kin = (const float*)d_in[1];
    const float* Vin = (const float*)d_in[2];
    const float* WQw = (const float*)d_in[3];
    const float* WQb = (const float*)d_in[4];
    const float* WKw = (const float*)d_in[5];
    const float* WKb = (const float*)d_in[6];
    const float* WVw = (const float*)d_in[7];
    const float* WVb = (const float*)d_in[8];
    const float* WOw = (const float*)d_in[9];
    const float* WOb = (const float*)d_in[10];
    float* Out = (float*)d_out;

    float *qp, *kp, *vp, *zp;
    cudaGetSymbolAddress((void**)&qp, g_q);
    cudaGetSymbolAddress((void**)&kp, g_k);
    cudaGetSymbolAddress((void**)&vp, g_v);
    cudaGetSymbolAddress((void**)&zp, g_z);

    dim3 blk(256);

    // 1) Q/K/V projections: [2048,1024] @ [1024,1024]^T + bias
    dim3 gproj(D_MODEL / 128, S_LEN / 128);
    sgemm_nt_bias<<<gproj, blk>>>(Qin, WQw, WQb, qp, D_MODEL, D_MODEL, D_MODEL, D_MODEL);
    sgemm_nt_bias<<<gproj, blk>>>(Kin, WKw, WKb, kp, D_MODEL, D_MODEL, D_MODEL, D_MODEL);
    sgemm_nt_bias<<<gproj, blk>>>(Vin, WVw, WVb, vp, D_MODEL, D_MODEL, D_MODEL, D_MODEL);

    // 2) masked QK^T per head (lower-triangle tiles only)
    dim3 gqk(S_LEN / 128, S_LEN / 128, NHEAD);
    sgemm_qk<<<gqk, blk>>>();

    // 3) per-column logsumexp -> L
    dim3 glse(S_LEN / 256, NHEAD);
    col_lse_kernel<<<glse, blk>>>();

    // 4) c = L^T V per head
    compute_c_kernel<<<NHEAD, blk>>>();

    // 5) attn = 0.125 * tril(QK) @ V - c  -> Z (head-major concat layout)
    dim3 gattn(S_LEN / 128, NHEAD);
    sgemm_attn<<<gattn, blk>>>();

    // 6) output projection: Z @ WOw^T + WOb
    dim3 gout(D_MODEL / 128, S_LEN / 128);
    sgemm_nt_bias<<<gout, blk>>>(zp, WOw, WOb, Out, D_MODEL, D_MODEL, D_MODEL, D_MODEL);
}

// round 4
// speedup vs baseline: 1.6503x; 1.6503x over previous
#include <cuda_runtime.h>
#include <cuda_bf16.h>
#include <stdint.h>
#include <math.h>

#define S_LEN   2048
#define D_MODEL 1024
#define NHEAD   16
#define HDIM    64

typedef __nv_bfloat16 bf16;

// ---------------------------------------------------------------------------
// Device-global scratch (allocation-free, zero-init at load).
// g_ph/g_pl strictly-upper-triangle tiles are NEVER written -> stay zero ->
// deterministic across graph replays.
// ---------------------------------------------------------------------------
static __device__ bf16  g_iqh[S_LEN * D_MODEL], g_iql[S_LEN * D_MODEL];
static __device__ bf16  g_ikh[S_LEN * D_MODEL], g_ikl[S_LEN * D_MODEL];
static __device__ bf16  g_ivh[S_LEN * D_MODEL], g_ivl[S_LEN * D_MODEL];
static __device__ bf16  g_wqh[D_MODEL * D_MODEL], g_wql[D_MODEL * D_MODEL];
static __device__ bf16  g_wkh[D_MODEL * D_MODEL], g_wkl[D_MODEL * D_MODEL];
static __device__ bf16  g_wvh[D_MODEL * D_MODEL], g_wvl[D_MODEL * D_MODEL];
static __device__ bf16  g_woh[D_MODEL * D_MODEL], g_wol[D_MODEL * D_MODEL];
static __device__ bf16  g_qh[S_LEN * D_MODEL], g_ql[S_LEN * D_MODEL];
static __device__ bf16  g_kh[S_LEN * D_MODEL], g_kl[S_LEN * D_MODEL];
static __device__ bf16  g_vth[D_MODEL * S_LEN], g_vtl[D_MODEL * S_LEN];  // [hv][t]
static __device__ bf16  g_ph[(size_t)NHEAD * S_LEN * S_LEN];
static __device__ bf16  g_pl[(size_t)NHEAD * S_LEN * S_LEN];
static __device__ bf16  g_zh[S_LEN * D_MODEL], g_zl[S_LEN * D_MODEL];
static __device__ float g_L[NHEAD * S_LEN];
static __device__ float g_c[NHEAD * HDIM];

// ---------------------------------------------------------------------------
// PTX helpers (all generic sm_80-class PTX -> legal under compute_103)
// ---------------------------------------------------------------------------
__device__ __forceinline__ uint32_t smem_u32(const void* p) {
    uint32_t a;
    asm("{ .reg .u64 t; cvta.to.shared.u64 t, %1; cvt.u32.u64 %0, t; }" : "=r"(a) : "l"(p));
    return a;
}
__device__ __forceinline__ void cp_async16(uint32_t dst, const void* src) {
    asm volatile("cp.async.cg.shared.global [%0], [%1], 16;" :: "r"(dst), "l"(src));
}
__device__ __forceinline__ void cp_commit() {
    asm volatile("cp.async.commit_group;" ::: "memory");
}
template<int N> __device__ __forceinline__ void cp_wait() {
    asm volatile("cp.async.wait_group %0;" :: "n"(N) : "memory");
}

#define LDSM_X4(r, addr) \
    asm volatile("ldmatrix.sync.aligned.m8n8.x4.shared.b16 {%0,%1,%2,%3}, [%4];" \
        : "=r"((r)[0]), "=r"((r)[1]), "=r"((r)[2]), "=r"((r)[3]) : "r"(addr))

__device__ __forceinline__ void mma16816(float* c, const uint32_t* a, const uint32_t* b) {
    asm volatile(
        "mma.sync.aligned.m16n8k16.row.col.f32.bf16.bf16.f32 "
        "{%0,%1,%2,%3}, {%4,%5,%6,%7}, {%8,%9}, {%0,%1,%2,%3};"
        : "+f"(c[0]), "+f"(c[1]), "+f"(c[2]), "+f"(c[3])
        : "r"(a[0]), "r"(a[1]), "r"(a[2]), "r"(a[3]), "r"(b[0]), "r"(b[1]));
}

__device__ __forceinline__ uint32_t split2(float v0, float v1, uint32_t& lopack) {
    bf16 h0 = __float2bfloat16(v0);
    bf16 h1 = __float2bfloat16(v1);
    bf16 l0 = __float2bfloat16(v0 - __bfloat162float(h0));
    bf16 l1 = __float2bfloat16(v1 - __bfloat162float(h1));
    lopack = (uint32_t)__bfloat16_as_ushort(l0) | ((uint32_t)__bfloat16_as_ushort(l1) << 16);
    return   (uint32_t)__bfloat16_as_ushort(h0) | ((uint32_t)__bfloat16_as_ushort(h1) << 16);
}

// ---------------------------------------------------------------------------
// Shared mma.sync mainloop. CTA tile 128 x BN, K chunks of 32 bf16.
// SMEM row pitch 40 bf16 (80B): conflict-free ldmatrix, 16B-aligned cp.async.
// 3-pass split-bf16: acc += Ahi*Bhi + Ahi*Blo + Alo*Bhi, fp32 accumulators.
// 8 warps: warp_m = wid&3 (32 rows each), warp_n = wid>>2 (BN/2 cols each).
// ---------------------------------------------------------------------------
#define PITCHB 80

template<int BN>
__device__ __forceinline__ void mma_mainloop(
    uint32_t sb, float (&acc)[2][BN/16][4],
    const bf16* __restrict__ Ahi, const bf16* __restrict__ Alo, int lda, int arow0,
    const bf16* __restrict__ Bhi, const bf16* __restrict__ Blo, int ldb, int brow0,
    int nchunks)
{
    constexpr int AB = 128 * PITCHB;
    constexpr int BB = BN * PITCHB;
    constexpr int STAGE = 2 * AB + 2 * BB;
    constexpr int NF = BN / 16;
    const int tid = threadIdx.x, lane = tid & 31, wid = tid >> 5;
    const int wm = (wid & 3) * 32, wn = (wid >> 2) * (BN / 2);

    auto load = [&](int c) {
        uint32_t s = sb + (uint32_t)(c & 1) * STAGE;
        const int k0 = c * 32;
        for (int i = tid; i < 128 * 4; i += 256) {
            int r = i >> 2, cb = (i & 3) << 4;
            uint32_t d = s + (uint32_t)(r * PITCHB + cb);
            cp_async16(d,      (const char*)(Ahi + (size_t)(arow0 + r) * lda + k0) + cb);
            cp_async16(d + AB, (const char*)(Alo + (size_t)(arow0 + r) * lda + k0) + cb);
        }
        for (int i = tid; i < BN * 4; i += 256) {
            int r = i >> 2, cb = (i & 3) << 4;
            uint32_t d = s + 2 * AB + (uint32_t)(r * PITCHB + cb);
            cp_async16(d,      (const char*)(Bhi + (size_t)(brow0 + r) * ldb + k0) + cb);
            cp_async16(d + BB, (const char*)(Blo + (size_t)(brow0 + r) * ldb + k0) + cb);
        }
        cp_commit();
    };

    // lane-fixed ldmatrix address offsets
    const uint32_t aoff = (uint32_t)((wm + (lane & 15)) * PITCHB + ((lane & 16) ? 16 : 0));
    const uint32_t boff = (uint32_t)((wn + (lane & 7) + ((lane & 16) ? 8 : 0)) * PITCHB +
                                     ((lane & 8) ? 16 : 0));

    load(0);
    for (int c = 0; c < nchunks; c++) {
        if (c + 1 < nchunks) { load(c + 1); cp_wait<1>(); }
        else                 { cp_wait<0>(); }
        __syncthreads();
        uint32_t s  = sb + (uint32_t)(c & 1) * STAGE;
        uint32_t sa = s + aoff;
        uint32_t sbb = s + 2 * AB + boff;
#pragma unroll
        for (int ks = 0; ks < 2; ks++) {
            const uint32_t ko = (uint32_t)(ks * 32);   // 16 bf16 = 32 bytes
            uint32_t ah[2][4], al[2][4];
            LDSM_X4(ah[0], sa + ko);
            LDSM_X4(ah[1], sa + 16 * PITCHB + ko);
            LDSM_X4(al[0], sa + AB + ko);
            LDSM_X4(al[1], sa + AB + 16 * PITCHB + ko);
            uint32_t bh[NF][2], bl[NF][2];
#pragma unroll
            for (int p = 0; p < NF / 2; p++) {
                uint32_t r4[4];
                LDSM_X4(r4, sbb + (uint32_t)(p * 16 * PITCHB) + ko);
                bh[2*p][0] = r4[0]; bh[2*p][1] = r4[1];
                bh[2*p+1][0] = r4[2]; bh[2*p+1][1] = r4[3];
                LDSM_X4(r4, sbb + BB + (uint32_t)(p * 16 * PITCHB) + ko);
                bl[2*p][0] = r4[0]; bl[2*p][1] = r4[1];
                bl[2*p+1][0] = r4[2]; bl[2*p+1][1] = r4[3];
            }
#pragma unroll
            for (int f = 0; f < 2; f++)
#pragma unroll
                for (int j = 0; j < NF; j++)
                    mma16816(acc[f][j], ah[f], bh[j]);
#pragma unroll
            for (int f = 0; f < 2; f++)
#pragma unroll
                for (int j = 0; j < NF; j++)
                    mma16816(acc[f][j], ah[f], bl[j]);
#pragma unroll
            for (int f = 0; f < 2; f++)
#pragma unroll
                for (int j = 0; j < NF; j++)
                    mma16816(acc[f][j], al[f], bh[j]);
        }
        __syncthreads();
    }
}

#define SMEM128 (2 * (2 * 128 * PITCHB + 2 * 128 * PITCHB))  // 81920
#define SMEM64  (2 * (2 * 128 * PITCHB + 2 * 64 * PITCHB))   // 61440

// ---------------------------------------------------------------------------
// Projection GEMM: C[2048,1024] = A*B^T + bias.
// MODE 0: bf16 hi/lo row-major   MODE 1: hi/lo transposed [col][row]
// MODE 2: fp32 row-major
// ---------------------------------------------------------------------------
template<int MODE>
__global__ __launch_bounds__(256) void gemm_proj(
    const bf16* __restrict__ Ahi, const bf16* __restrict__ Alo,
    const bf16* __restrict__ Bhi, const bf16* __restrict__ Blo,
    const float* __restrict__ bias,
    bf16* __restrict__ ohi, bf16* __restrict__ olo, float* __restrict__ ofp)
{
    extern __shared__ char smem[];
    uint32_t sb = smem_u32(smem);
    const int row0 = blockIdx.y << 7, col0 = blockIdx.x << 7;
    float acc[2][8][4];
#pragma unroll
    for (int f = 0; f < 2; f++)
#pragma unroll
        for (int j = 0; j < 8; j++)
#pragma unroll
            for (int q = 0; q < 4; q++) acc[f][j][q] = 0.f;

    mma_mainloop<128>(sb, acc, Ahi, Alo, D_MODEL, row0, Bhi, Blo, D_MODEL, col0, D_MODEL / 32);

    const int lane = threadIdx.x & 31, wid = threadIdx.x >> 5;
    const int wm = (wid & 3) * 32, wn = (wid >> 2) * 64;
    const int rb = row0 + wm + (lane >> 2);
    const int cb = col0 + wn + (lane & 3) * 2;
#pragma unroll
    for (int f = 0; f < 2; f++)
#pragma unroll
        for (int j = 0; j < 8; j++)
#pragma unroll
            for (int rh = 0; rh < 2; rh++) {
                const int r = rb + f * 16 + rh * 8;
                const int col = cb + j * 8;
                float v0 = acc[f][j][rh * 2 + 0];
                float v1 = acc[f][j][rh * 2 + 1];
                if (MODE == 2) {
                    v0 += bias[col]; v1 += bias[col + 1];
                    *(float2*)(ofp + (size_t)r * D_MODEL + col) = make_float2(v0, v1);
                } else if (MODE == 1) {
                    v0 += bias[col]; v1 += bias[col + 1];
                    bf16 h0 = __float2bfloat16(v0);
                    bf16 h1 = __float2bfloat16(v1);
                    ohi[(size_t)col * S_LEN + r]       = h0;
                    ohi[(size_t)(col + 1) * S_LEN + r] = h1;
                    olo[(size_t)col * S_LEN + r]       = __float2bfloat16(v0 - __bfloat162float(h0));
                    olo[(size_t)(col + 1) * S_LEN + r] = __float2bfloat16(v1 - __bfloat162float(h1));
                } else {
                    v0 += bias[col]; v1 += bias[col + 1];
                    uint32_t lp, hp = split2(v0, v1, lp);
                    *(uint32_t*)(ohi + (size_t)r * D_MODEL + col) = hp;
                    *(uint32_t*)(olo + (size_t)r * D_MODEL + col) = lp;
                }
            }
}

// ---------------------------------------------------------------------------
// Causal QK^T per head -> P hi/lo. grid(16,16,16): bx=t-tile, by=s-tile, bz=h.
// ---------------------------------------------------------------------------
__global__ __launch_bounds__(256) void gemm_qk_tc()
{
    if (blockIdx.x > blockIdx.y) return;
    extern __shared__ char smem[];
    uint32_t sb = smem_u32(smem);
    const int h = blockIdx.z;
    const int row0 = blockIdx.y << 7, col0 = blockIdx.x << 7;
    float acc[2][8][4];
#pragma unroll
    for (int f = 0; f < 2; f++)
#pragma unroll
        for (int j = 0; j < 8; j++)
#pragma unroll
            for (int q = 0; q < 4; q++) acc[f][j][q] = 0.f;

    mma_mainloop<128>(sb, acc,
                      g_qh + h * HDIM, g_ql + h * HDIM, D_MODEL, row0,
                      g_kh + h * HDIM, g_kl + h * HDIM, D_MODEL, col0, HDIM / 32);

    bf16* phi = g_ph + (size_t)h * S_LEN * S_LEN;
    bf16* plo = g_pl + (size_t)h * S_LEN * S_LEN;
    const int lane = threadIdx.x & 31, wid = threadIdx.x >> 5;
    const int wm = (wid & 3) * 32, wn = (wid >> 2) * 64;
    const int rb = row0 + wm + (lane >> 2);
    const int cb = col0 + wn + (lane & 3) * 2;
#pragma unroll
    for (int f = 0; f < 2; f++)
#pragma unroll
        for (int j = 0; j < 8; j++)
#pragma unroll
            for (int rh = 0; rh < 2; rh++) {
                const int r = rb + f * 16 + rh * 8;
                const int col = cb + j * 8;
                float v0 = (col     <= r) ? acc[f][j][rh * 2 + 0] : 0.f;
                float v1 = (col + 1 <= r) ? acc[f][j][rh * 2 + 1] : 0.f;
                uint32_t lp, hp = split2(v0, v1, lp);
                *(uint32_t*)(phi + (size_t)r * S_LEN + col) = hp;
                *(uint32_t*)(plo + (size_t)r * S_LEN + col) = lp;
            }
}

// ---------------------------------------------------------------------------
// P @ V per head (triangular): Z = 0.125 * P Vt^T - c, written hi/lo.
// grid(16 s-tiles, 16 heads). CTA tile 128x64.
// ---------------------------------------------------------------------------
__global__ __launch_bounds__(256) void gemm_pv_tc()
{
    extern __shared__ char smem[];
    uint32_t sb = smem_u32(smem);
    const int h = blockIdx.y;
    const int row0 = blockIdx.x << 7;
    const int nchunks = (row0 + 128) / 32;
    float acc[2][4][4];
#pragma unroll
    for (int f = 0; f < 2; f++)
#pragma unroll
        for (int j = 0; j < 4; j++)
#pragma unroll
            for (int q = 0; q < 4; q++) acc[f][j][q] = 0.f;

    mma_mainloop<64>(sb, acc,
                     g_ph + (size_t)h * S_LEN * S_LEN, g_pl + (size_t)h * S_LEN * S_LEN,
                     S_LEN, row0,
                     g_vth + (size_t)h * HDIM * S_LEN, g_vtl + (size_t)h * HDIM * S_LEN,
                     S_LEN, 0, nchunks);

    const int lane = threadIdx.x & 31, wid = threadIdx.x >> 5;
    const int wm = (wid & 3) * 32, wn = (wid >> 2) * 32;
    const int rb = row0 + wm + (lane >> 2);
    const int cb = wn + (lane & 3) * 2;          // 0..63 within head
#pragma unroll
    for (int f = 0; f < 2; f++)
#pragma unroll
        for (int j = 0; j < 4; j++)
#pragma unroll
            for (int rh = 0; rh < 2; rh++) {
                const int r = rb + f * 16 + rh * 8;
                const int cc = cb + j * 8;
                float v0 = acc[f][j][rh * 2 + 0] * 0.125f - g_c[h * HDIM + cc];
                float v1 = acc[f][j][rh * 2 + 1] * 0.125f - g_c[h * HDIM + cc + 1];
                uint32_t lp, hp = split2(v0, v1, lp);
                size_t off = (size_t)r * D_MODEL + h * HDIM + cc;
                *(uint32_t*)(g_zh + off) = hp;
                *(uint32_t*)(g_zl + off) = lp;
            }
}

// ---------------------------------------------------------------------------
// Column logsumexp: L[h][t] = log( s0 + sum_{s>=s0} exp((Phi+Plo)[s][t]/8) )
// ---------------------------------------------------------------------------
__global__ __launch_bounds__(256) void col_lse_tc()
{
    const int h  = blockIdx.y;
    const int t  = (blockIdx.x << 8) + threadIdx.x;
    const int s0 = blockIdx.x << 8;
    const bf16* bh = g_ph + (size_t)h * S_LEN * S_LEN + t;
    const bf16* bl = g_pl + (size_t)h * S_LEN * S_LEN + t;

    float a0 = 0.f, a1 = 0.f, a2 = 0.f, a3 = 0.f;
    for (int s = s0; s < S_LEN; s += 4) {
        float v0 = __bfloat162float(bh[(size_t)(s+0)*S_LEN]) + __bfloat162float(bl[(size_t)(s+0)*S_LEN]);
        float v1 = __bfloat162float(bh[(size_t)(s+1)*S_LEN]) + __bfloat162float(bl[(size_t)(s+1)*S_LEN]);
        float v2 = __bfloat162float(bh[(size_t)(s+2)*S_LEN]) + __bfloat162float(bl[(size_t)(s+2)*S_LEN]);
        float v3 = __bfloat162float(bh[(size_t)(s+3)*S_LEN]) + __bfloat162float(bl[(size_t)(s+3)*S_LEN]);
        a0 += expf(v0 * 0.125f);
        a1 += expf(v1 * 0.125f);
        a2 += expf(v2 * 0.125f);
        a3 += expf(v3 * 0.125f);
    }
    g_L[h * S_LEN + t] = logf((float)s0 + ((a0 + a1) + (a2 + a3)));
}

// ---------------------------------------------------------------------------
// c[h][v] = sum_t L[h][t] * V[t][h*64+v]   (reads transposed V splits)
// ---------------------------------------------------------------------------
__global__ __launch_bounds__(256) void compute_c_tc()
{
    __shared__ float part[4][HDIM];
    const int h = blockIdx.x;
    const int v = threadIdx.x & 63;
    const int g = threadIdx.x >> 6;
    const bf16* th = g_vth + (size_t)(h * HDIM + v) * S_LEN;
    const bf16* tl = g_vtl + (size_t)(h * HDIM + v) * S_LEN;
    const float* Lh = g_L + h * S_LEN;
    float sum = 0.f;
    const int t0 = g * (S_LEN / 4);
    for (int t = t0; t < t0 + S_LEN / 4; t++)
        sum = fmaf(Lh[t], __bfloat162float(th[t]) + __bfloat162float(tl[t]), sum);
    part[g][v] = sum;
    __syncthreads();
    if (g == 0)
        g_c[h * HDIM + v] = (part[0][v] + part[1][v]) + (part[2][v] + part[3][v]);
}

// ---------------------------------------------------------------------------
// fp32 -> bf16 hi/lo split
// ---------------------------------------------------------------------------
__global__ __launch_bounds__(256) void split_kernel(
    const float* __restrict__ src, uint32_t* __restrict__ hi, uint32_t* __restrict__ lo, int npairs)
{
    int i = blockIdx.x * 256 + threadIdx.x;
    if (i < npairs) {
        float2 v = ((const float2*)src)[i];
        uint32_t l;
        uint32_t h = split2(v.x, v.y, l);
        hi[i] = h; lo[i] = l;
    }
}

// ---------------------------------------------------------------------------
extern "C" void kernel_launch(void* const* d_in, const int* in_sizes, int n_in,
                              void* d_out, int out_size)
{
    const float* Qin = (const float*)d_in[0];
    const float* Kin = (const float*)d_in[1];
    const float* Vin = (const float*)d_in[2];
    const float* WQw = (const float*)d_in[3];
    const float* WQb = (const float*)d_in[4];
    const float* WKw = (const float*)d_in[5];
    const float* WKb = (const float*)d_in[6];
    const float* WVw = (const float*)d_in[7];
    const float* WVb = (const float*)d_in[8];
    const float* WOw = (const float*)d_in[9];
    const float* WOb = (const float*)d_in[10];
    float* Out = (float*)d_out;

#define GETP(name, sym) void* name; cudaGetSymbolAddress(&name, sym)
    GETP(iqh, g_iqh); GETP(iql, g_iql); GETP(ikh, g_ikh); GETP(ikl, g_ikl);
    GETP(ivh, g_ivh); GETP(ivl, g_ivl);
    GETP(wqh, g_wqh); GETP(wql, g_wql); GETP(wkh, g_wkh); GETP(wkl, g_wkl);
    GETP(wvh, g_wvh); GETP(wvl, g_wvl); GETP(woh, g_woh); GETP(wol, g_wol);
    GETP(qh, g_qh);   GETP(ql, g_ql);   GETP(kh, g_kh);   GETP(kl, g_kl);
    GETP(vth, g_vth); GETP(vtl, g_vtl);
    GETP(zh, g_zh);   GETP(zl, g_zl);
#undef GETP

    static int attr_done = 0;
    cudaFuncSetAttribute(gemm_proj<0>, cudaFuncAttributeMaxDynamicSharedMemorySize, SMEM128);
    cudaFuncSetAttribute(gemm_proj<1>, cudaFuncAttributeMaxDynamicSharedMemorySize, SMEM128);
    cudaFuncSetAttribute(gemm_proj<2>, cudaFuncAttributeMaxDynamicSharedMemorySize, SMEM128);
    cudaFuncSetAttribute(gemm_qk_tc,   cudaFuncAttributeMaxDynamicSharedMemorySize, SMEM128);
    cudaFuncSetAttribute(gemm_pv_tc,   cudaFuncAttributeMaxDynamicSharedMemorySize, SMEM64);
    (void)attr_done;

    const int npIn = S_LEN * D_MODEL / 2;
    const int npW  = D_MODEL * D_MODEL / 2;
    dim3 blk(256);

    // 1) hi/lo splits of inputs and weights
    split_kernel<<<npIn / 256, blk>>>(Qin, (uint32_t*)iqh, (uint32_t*)iql, npIn);
    split_kernel<<<npIn / 256, blk>>>(Kin, (uint32_t*)ikh, (uint32_t*)ikl, npIn);
    split_kernel<<<npIn / 256, blk>>>(Vin, (uint32_t*)ivh, (uint32_t*)ivl, npIn);
    split_kernel<<<npW / 256, blk>>>(WQw, (uint32_t*)wqh, (uint32_t*)wql, npW);
    split_kernel<<<npW / 256, blk>>>(WKw, (uint32_t*)wkh, (uint32_t*)wkl, npW);
    split_kernel<<<npW / 256, blk>>>(WVw, (uint32_t*)wvh, (uint32_t*)wvl, npW);
    split_kernel<<<npW / 256, blk>>>(WOw, (uint32_t*)woh, (uint32_t*)wol, npW);

    // 2) projections
    dim3 gproj(D_MODEL / 128, S_LEN / 128);
    gemm_proj<0><<<gproj, blk, SMEM128>>>((bf16*)iqh, (bf16*)iql, (bf16*)wqh, (bf16*)wql,
                                          WQb, (bf16*)qh, (bf16*)ql, nullptr);
    gemm_proj<0><<<gproj, blk, SMEM128>>>((bf16*)ikh, (bf16*)ikl, (bf16*)wkh, (bf16*)wkl,
                                          WKb, (bf16*)kh, (bf16*)kl, nullptr);
    gemm_proj<1><<<gproj, blk, SMEM128>>>((bf16*)ivh, (bf16*)ivl, (bf16*)wvh, (bf16*)wvl,
                                          WVb, (bf16*)vth, (bf16*)vtl, nullptr);

    // 3) causal QK^T -> P hi/lo (lower-triangle tiles only)
    dim3 gqk(S_LEN / 128, S_LEN / 128, NHEAD);
    gemm_qk_tc<<<gqk, blk, SMEM128>>>();

    // 4) column LSE, 5) c = L^T V
    dim3 glse(S_LEN / 256, NHEAD);
    col_lse_tc<<<glse, blk>>>();
    compute_c_tc<<<NHEAD, blk>>>();

    // 6) Z = 0.125 * P V - c  (hi/lo for the output projection)
    dim3 gpv(S_LEN / 128, NHEAD);
    gemm_pv_tc<<<gpv, blk, SMEM64>>>();

    // 7) output projection -> d_out
    gemm_proj<2><<<gproj, blk, SMEM128>>>((bf16*)zh, (bf16*)zl, (bf16*)woh, (bf16*)wol,
                                          WOb, nullptr, nullptr, Out);
}

// round 5
// speedup vs baseline: 2.7826x; 1.6861x over previous
#include <cuda_runtime.h>
#include <cuda_bf16.h>
#include <stdint.h>
#include <math.h>

#define S_LEN   2048
#define D_MODEL 1024
#define NHEAD   16
#define HDIM    64

typedef __nv_bfloat16 bf16;

// ---------------------------------------------------------------------------
// Device-global scratch (allocation-free, zero-init at load).
// ---------------------------------------------------------------------------
static __device__ bf16  g_iqh[S_LEN * D_MODEL], g_iql[S_LEN * D_MODEL];
static __device__ bf16  g_ikh[S_LEN * D_MODEL], g_ikl[S_LEN * D_MODEL];
static __device__ bf16  g_ivh[S_LEN * D_MODEL], g_ivl[S_LEN * D_MODEL];
static __device__ bf16  g_wqh[D_MODEL * D_MODEL], g_wql[D_MODEL * D_MODEL];
static __device__ bf16  g_wkh[D_MODEL * D_MODEL], g_wkl[D_MODEL * D_MODEL];
static __device__ bf16  g_wvh[D_MODEL * D_MODEL], g_wvl[D_MODEL * D_MODEL];
static __device__ bf16  g_woh[D_MODEL * D_MODEL], g_wol[D_MODEL * D_MODEL];
static __device__ bf16  g_qh[S_LEN * D_MODEL], g_ql[S_LEN * D_MODEL];
static __device__ bf16  g_kh[S_LEN * D_MODEL], g_kl[S_LEN * D_MODEL];
static __device__ bf16  g_vth[D_MODEL * S_LEN], g_vtl[D_MODEL * S_LEN];  // [h*64+v][t]
static __device__ bf16  g_zh[S_LEN * D_MODEL], g_zl[S_LEN * D_MODEL];
static __device__ float g_part[NHEAD * 16 * S_LEN];   // [h][sblock][t] partial exp sums
static __device__ float g_L[NHEAD * S_LEN];
static __device__ float g_c[NHEAD * HDIM];
static __device__ float g_badj[D_MODEL];

// ---------------------------------------------------------------------------
// PTX helpers (generic sm_80-class PTX, legal under compute_103)
// ---------------------------------------------------------------------------
__device__ __forceinline__ uint32_t smem_u32(const void* p) {
    uint32_t a;
    asm("{ .reg .u64 t; cvta.to.shared.u64 t, %1; cvt.u32.u64 %0, t; }" : "=r"(a) : "l"(p));
    return a;
}
__device__ __forceinline__ void cp_async16(uint32_t dst, const void* src) {
    asm volatile("cp.async.cg.shared.global [%0], [%1], 16;" :: "r"(dst), "l"(src));
}
__device__ __forceinline__ void cp_commit() {
    asm volatile("cp.async.commit_group;" ::: "memory");
}
template<int N> __device__ __forceinline__ void cp_wait() {
    asm volatile("cp.async.wait_group %0;" :: "n"(N) : "memory");
}

#define LDSM_X4(r, addr) \
    asm volatile("ldmatrix.sync.aligned.m8n8.x4.shared.b16 {%0,%1,%2,%3}, [%4];" \
        : "=r"((r)[0]), "=r"((r)[1]), "=r"((r)[2]), "=r"((r)[3]) : "r"(addr))

__device__ __forceinline__ void mma16816(float* c, const uint32_t* a, const uint32_t* b) {
    asm volatile(
        "mma.sync.aligned.m16n8k16.row.col.f32.bf16.bf16.f32 "
        "{%0,%1,%2,%3}, {%4,%5,%6,%7}, {%8,%9}, {%0,%1,%2,%3};"
        : "+f"(c[0]), "+f"(c[1]), "+f"(c[2]), "+f"(c[3])
        : "r"(a[0]), "r"(a[1]), "r"(a[2]), "r"(a[3]), "r"(b[0]), "r"(b[1]));
}

__device__ __forceinline__ uint32_t split2(float v0, float v1, uint32_t& lopack) {
    bf16 h0 = __float2bfloat16(v0);
    bf16 h1 = __float2bfloat16(v1);
    bf16 l0 = __float2bfloat16(v0 - __bfloat162float(h0));
    bf16 l1 = __float2bfloat16(v1 - __bfloat162float(h1));
    lopack = (uint32_t)__bfloat16_as_ushort(l0) | ((uint32_t)__bfloat16_as_ushort(l1) << 16);
    return   (uint32_t)__bfloat16_as_ushort(h0) | ((uint32_t)__bfloat16_as_ushort(h1) << 16);
}

// exp on the FMA pipe (no MUFU): exp(x) = 2^(x*log2e), deg-5 Taylor on 2^f
__device__ __forceinline__ float exp_poly(float x) {
    float y  = x * 1.4426950408889634f;
    float fy = y + 12582912.0f;                 // round to nearest int
    float n  = fy - 12582912.0f;
    float f  = y - n;                           // [-0.5, 0.5]
    float p = fmaf(0.00133336f, f, 0.00961813f);
    p = fmaf(p, f, 0.05550411f);
    p = fmaf(p, f, 0.24022651f);
    p = fmaf(p, f, 0.69314718f);
    p = fmaf(p, f, 1.0f);
    return __int_as_float(__float_as_int(p) + (__float_as_int(fy) << 23));
}

// ---------------------------------------------------------------------------
// Projection GEMM machinery: 128x128 tile, BK=32, 3-stage cp.async pipeline.
// 3-pass split-bf16: acc += Ahi*Bhi + Ahi*Blo + Alo*Bhi, fp32 accumulators.
// 8 warps: warp_m = wid&3 (32 rows), warp_n = wid>>2 (64 cols).
// ---------------------------------------------------------------------------
#define PITCHB 80

__device__ __forceinline__ void mma_mainloop128(
    uint32_t sb, float (&acc)[2][8][4],
    const bf16* __restrict__ Ahi, const bf16* __restrict__ Alo, int lda, int arow0,
    const bf16* __restrict__ Bhi, const bf16* __restrict__ Blo, int ldb, int brow0,
    int nchunks)
{
    constexpr int AB = 128 * PITCHB;
    constexpr int BB = 128 * PITCHB;
    constexpr int STAGE = 2 * AB + 2 * BB;        // 40960
    const int tid = threadIdx.x, lane = tid & 31, wid = tid >> 5;
    const int wm = (wid & 3) * 32, wn = (wid >> 2) * 64;

    auto load = [&](int c) {
        uint32_t s = sb + (uint32_t)(c % 3) * STAGE;
        const int k0 = c * 32;
        for (int i = tid; i < 128 * 4; i += 256) {
            int r = i >> 2, cb = (i & 3) << 4;
            uint32_t d = s + (uint32_t)(r * PITCHB + cb);
            cp_async16(d,      (const char*)(Ahi + (size_t)(arow0 + r) * lda + k0) + cb);
            cp_async16(d + AB, (const char*)(Alo + (size_t)(arow0 + r) * lda + k0) + cb);
        }
        for (int i = tid; i < 128 * 4; i += 256) {
            int r = i >> 2, cb = (i & 3) << 4;
            uint32_t d = s + 2 * AB + (uint32_t)(r * PITCHB + cb);
            cp_async16(d,      (const char*)(Bhi + (size_t)(brow0 + r) * ldb + k0) + cb);
            cp_async16(d + BB, (const char*)(Blo + (size_t)(brow0 + r) * ldb + k0) + cb);
        }
        cp_commit();
    };

    const uint32_t aoff = (uint32_t)((wm + (lane & 15)) * PITCHB + ((lane & 16) ? 16 : 0));
    const uint32_t boff = (uint32_t)((wn + (lane & 7) + ((lane & 16) ? 8 : 0)) * PITCHB +
                                     ((lane & 8) ? 16 : 0));

    load(0);
    if (nchunks > 1) load(1);
    for (int c = 0; c < nchunks; c++) {
        if (c + 2 < nchunks) { load(c + 2); cp_wait<2>(); }
        else if (c + 1 < nchunks) cp_wait<1>();
        else cp_wait<0>();
        __syncthreads();
        uint32_t s  = sb + (uint32_t)(c % 3) * STAGE;
        uint32_t sa = s + aoff;
        uint32_t sbb = s + 2 * AB + boff;
#pragma unroll
        for (int ks = 0; ks < 2; ks++) {
            const uint32_t ko = (uint32_t)(ks * 32);
            uint32_t ah[2][4], al[2][4];
            LDSM_X4(ah[0], sa + ko);
            LDSM_X4(ah[1], sa + 16 * PITCHB + ko);
            LDSM_X4(al[0], sa + AB + ko);
            LDSM_X4(al[1], sa + AB + 16 * PITCHB + ko);
            uint32_t bh[8][2], bl[8][2];
#pragma unroll
            for (int p = 0; p < 4; p++) {
                uint32_t r4[4];
                LDSM_X4(r4, sbb + (uint32_t)(p * 16 * PITCHB) + ko);
                bh[2*p][0] = r4[0]; bh[2*p][1] = r4[1];
                bh[2*p+1][0] = r4[2]; bh[2*p+1][1] = r4[3];
                LDSM_X4(r4, sbb + BB + (uint32_t)(p * 16 * PITCHB) + ko);
                bl[2*p][0] = r4[0]; bl[2*p][1] = r4[1];
                bl[2*p+1][0] = r4[2]; bl[2*p+1][1] = r4[3];
            }
#pragma unroll
            for (int f = 0; f < 2; f++)
#pragma unroll
                for (int j = 0; j < 8; j++)
                    mma16816(acc[f][j], ah[f], bh[j]);
#pragma unroll
            for (int f = 0; f < 2; f++)
#pragma unroll
                for (int j = 0; j < 8; j++)
                    mma16816(acc[f][j], ah[f], bl[j]);
#pragma unroll
            for (int f = 0; f < 2; f++)
#pragma unroll
                for (int j = 0; j < 8; j++)
                    mma16816(acc[f][j], al[f], bh[j]);
        }
        __syncthreads();
    }
}

#define SMEM_PROJ (3 * (2 * 128 * PITCHB + 2 * 128 * PITCHB))   // 122880

// ---------------------------------------------------------------------------
// Projection GEMM: C[2048,1024] = A*B^T + bias.
// MODE 0: bf16 hi/lo row-major   MODE 1: hi/lo transposed [col][row]
// MODE 2: fp32 row-major
// ---------------------------------------------------------------------------
template<int MODE>
__global__ __launch_bounds__(256) void gemm_proj(
    const bf16* __restrict__ Ahi, const bf16* __restrict__ Alo,
    const bf16* __restrict__ Bhi, const bf16* __restrict__ Blo,
    const float* __restrict__ bias,
    bf16* __restrict__ ohi, bf16* __restrict__ olo, float* __restrict__ ofp)
{
    extern __shared__ char smem[];
    uint32_t sb = smem_u32(smem);
    const int row0 = blockIdx.y << 7, col0 = blockIdx.x << 7;
    float acc[2][8][4];
#pragma unroll
    for (int f = 0; f < 2; f++)
#pragma unroll
        for (int j = 0; j < 8; j++)
#pragma unroll
            for (int q = 0; q < 4; q++) acc[f][j][q] = 0.f;

    mma_mainloop128(sb, acc, Ahi, Alo, D_MODEL, row0, Bhi, Blo, D_MODEL, col0, D_MODEL / 32);

    const int lane = threadIdx.x & 31, wid = threadIdx.x >> 5;
    const int wm = (wid & 3) * 32, wn = (wid >> 2) * 64;
    const int rb = row0 + wm + (lane >> 2);
    const int cb = col0 + wn + (lane & 3) * 2;
#pragma unroll
    for (int f = 0; f < 2; f++)
#pragma unroll
        for (int j = 0; j < 8; j++)
#pragma unroll
            for (int rh = 0; rh < 2; rh++) {
                const int r = rb + f * 16 + rh * 8;
                const int col = cb + j * 8;
                float v0 = acc[f][j][rh * 2 + 0] + bias[col];
                float v1 = acc[f][j][rh * 2 + 1] + bias[col + 1];
                if (MODE == 2) {
                    *(float2*)(ofp + (size_t)r * D_MODEL + col) = make_float2(v0, v1);
                } else if (MODE == 1) {
                    bf16 h0 = __float2bfloat16(v0);
                    bf16 h1 = __float2bfloat16(v1);
                    ohi[(size_t)col * S_LEN + r]       = h0;
                    ohi[(size_t)(col + 1) * S_LEN + r] = h1;
                    olo[(size_t)col * S_LEN + r]       = __float2bfloat16(v0 - __bfloat162float(h0));
                    olo[(size_t)(col + 1) * S_LEN + r] = __float2bfloat16(v1 - __bfloat162float(h1));
                } else {
                    uint32_t lp, hp = split2(v0, v1, lp);
                    *(uint32_t*)(ohi + (size_t)r * D_MODEL + col) = hp;
                    *(uint32_t*)(olo + (size_t)r * D_MODEL + col) = lp;
                }
            }
}

// ---------------------------------------------------------------------------
// Fused attention: per (s-block pair, head) CTA.
//   loop t-blocks <= s-block:
//     S = Q Kt^T (3-pass bf16 MMA, 16 rows/warp x 128 cols)
//     mask diagonal; exp partial column sums -> g_part (hybrid MUFU/poly exp)
//     O += S_bf16split @ V^T (3-pass MMA, fragments repacked in registers)
//   epilogue: Z = 0.125*O (hi/lo split; -c folded into out-proj bias)
// ---------------------------------------------------------------------------
#define PQB  144    // pitch bytes for 64-bf16-wide rows
#define PVB  272    // pitch bytes for 128-bf16-wide rows
#define QSZ  (128 * PQB)          // 18432
#define KSTG (2 * QSZ)            // hi+lo        36864
#define VSZ  (64 * PVB)           // 17408
#define VSTG (2 * VSZ)            // hi+lo        34816
#define OFF_K   (2 * QSZ)                         // 36864
#define OFF_V   (OFF_K + 2 * KSTG)                // 110592
#define OFF_PART (OFF_V + 2 * VSTG)               // 180224
#define FATTN_SMEM (OFF_PART + 8 * 128 * 4)       // 184320

__global__ __launch_bounds__(256) void fused_attn()
{
    extern __shared__ char smem[];
    uint32_t sb = smem_u32(smem);
    const int h = blockIdx.y;
    const int tid = threadIdx.x, lane = tid & 31, wid = tid >> 5;
    float* spart = (float*)(smem + OFF_PART);

    const uint32_t qoff = sb + (uint32_t)((wid * 16 + (lane & 15)) * PQB + ((lane & 16) ? 16 : 0));
    const uint32_t kvlane = (uint32_t)((lane & 7) + ((lane & 16) ? 8 : 0));
    const uint32_t koff_l = kvlane * PQB + ((lane & 8) ? 16 : 0);
    const uint32_t voff_l = kvlane * PVB + ((lane & 8) ? 16 : 0);

    for (int half = 0; half < 2; half++) {
        const int sblk = half ? (15 - (int)blockIdx.x) : (int)blockIdx.x;
        const int row0 = sblk << 7;
        const int ntb  = sblk + 1;

        // Q tile (128 x 64 bf16 hi/lo)
        for (int i = tid; i < 128 * 8; i += 256) {
            int r = i >> 3, cbyte = (i & 7) << 4;
            cp_async16(sb + (uint32_t)(r * PQB) + cbyte,
                       (const char*)(g_qh + (size_t)(row0 + r) * D_MODEL + h * HDIM) + cbyte);
            cp_async16(sb + QSZ + (uint32_t)(r * PQB) + cbyte,
                       (const char*)(g_ql + (size_t)(row0 + r) * D_MODEL + h * HDIM) + cbyte);
        }
        cp_commit();

        auto loadKV = [&](int tb) {
            uint32_t kbase = sb + OFF_K + (uint32_t)(tb & 1) * KSTG;
            uint32_t vbase = sb + OFF_V + (uint32_t)(tb & 1) * VSTG;
            const int col0 = tb << 7;
            for (int i = tid; i < 128 * 8; i += 256) {
                int r = i >> 3, cbyte = (i & 7) << 4;
                cp_async16(kbase + (uint32_t)(r * PQB) + cbyte,
                           (const char*)(g_kh + (size_t)(col0 + r) * D_MODEL + h * HDIM) + cbyte);
                cp_async16(kbase + QSZ + (uint32_t)(r * PQB) + cbyte,
                           (const char*)(g_kl + (size_t)(col0 + r) * D_MODEL + h * HDIM) + cbyte);
            }
            for (int i = tid; i < 64 * 16; i += 256) {
                int r = i >> 4, cbyte = (i & 15) << 4;
                cp_async16(vbase + (uint32_t)(r * PVB) + cbyte,
                           (const char*)(g_vth + (size_t)(h * HDIM + r) * S_LEN + col0) + cbyte);
                cp_async16(vbase + VSZ + (uint32_t)(r * PVB) + cbyte,
                           (const char*)(g_vtl + (size_t)(h * HDIM + r) * S_LEN + col0) + cbyte);
            }
            cp_commit();
        };
        loadKV(0);

        float oacc[8][4];
#pragma unroll
        for (int j = 0; j < 8; j++)
#pragma unroll
            for (int q = 0; q < 4; q++) oacc[j][q] = 0.f;

        for (int tb = 0; tb < ntb; tb++) {
            if (tb + 1 < ntb) { loadKV(tb + 1); cp_wait<1>(); }
            else              { cp_wait<0>(); }
            __syncthreads();

            uint32_t kbase = sb + OFF_K + (uint32_t)(tb & 1) * KSTG;
            uint32_t vbase = sb + OFF_V + (uint32_t)(tb & 1) * VSTG;

            // ---- MMA1: S[16 x 128] per warp ----
            float sacc[16][4];
#pragma unroll
            for (int j = 0; j < 16; j++)
#pragma unroll
                for (int q = 0; q < 4; q++) sacc[j][q] = 0.f;

            const uint32_t koff = kbase + koff_l;
#pragma unroll
            for (int ks = 0; ks < 4; ks++) {
                const uint32_t ko = (uint32_t)(ks * 32);
                uint32_t ah[4], al[4];
                LDSM_X4(ah, qoff + ko);
                LDSM_X4(al, qoff + QSZ + ko);
#pragma unroll
                for (int p = 0; p < 8; p++) {
                    uint32_t bh[4], bl[4];
                    LDSM_X4(bh, koff + (uint32_t)(p * 16 * PQB) + ko);
                    LDSM_X4(bl, koff + QSZ + (uint32_t)(p * 16 * PQB) + ko);
                    mma16816(sacc[2*p],   ah, bh);
                    mma16816(sacc[2*p+1], ah, bh + 2);
                    mma16816(sacc[2*p],   ah, bl);
                    mma16816(sacc[2*p+1], ah, bl + 2);
                    mma16816(sacc[2*p],   al, bh);
                    mma16816(sacc[2*p+1], al, bh + 2);
                }
            }

            // ---- mask + exp partial column sums ----
            const bool diag = (tb == sblk);
            const int r0 = row0 + wid * 16 + (lane >> 2);
            const int r1 = r0 + 8;
            const int cb2 = (tb << 7) + 2 * (lane & 3);
#pragma unroll
            for (int nf = 0; nf < 16; nf++) {
                const int c0 = cb2 + nf * 8;
                float s0 = sacc[nf][0], s1 = sacc[nf][1];
                float s2 = sacc[nf][2], s3 = sacc[nf][3];
                bool m0 = true, m1 = true, m2 = true, m3 = true;
                if (diag) {
                    m0 = (c0 <= r0); m1 = (c0 + 1 <= r0);
                    m2 = (c0 <= r1); m3 = (c0 + 1 <= r1);
                    s0 = m0 ? s0 : 0.f; s1 = m1 ? s1 : 0.f;
                    s2 = m2 ? s2 : 0.f; s3 = m3 ? s3 : 0.f;
                    sacc[nf][0] = s0; sacc[nf][1] = s1;
                    sacc[nf][2] = s2; sacc[nf][3] = s3;
                }
                float e0, e1, e2, e3;
                if (nf < 11) {               // ~2:1 MUFU : poly split
                    e0 = __expf(s0 * 0.125f); e1 = __expf(s1 * 0.125f);
                    e2 = __expf(s2 * 0.125f); e3 = __expf(s3 * 0.125f);
                } else {
                    e0 = exp_poly(s0 * 0.125f); e1 = exp_poly(s1 * 0.125f);
                    e2 = exp_poly(s2 * 0.125f); e3 = exp_poly(s3 * 0.125f);
                }
                if (diag) {
                    e0 = m0 ? e0 : 0.f; e1 = m1 ? e1 : 0.f;
                    e2 = m2 ? e2 : 0.f; e3 = m3 ? e3 : 0.f;
                }
                float eA = e0 + e2, eB = e1 + e3;
                eA += __shfl_xor_sync(0xffffffffu, eA, 4);
                eA += __shfl_xor_sync(0xffffffffu, eA, 8);
                eA += __shfl_xor_sync(0xffffffffu, eA, 16);
                eB += __shfl_xor_sync(0xffffffffu, eB, 4);
                eB += __shfl_xor_sync(0xffffffffu, eB, 8);
                eB += __shfl_xor_sync(0xffffffffu, eB, 16);
                if (lane < 4) {
                    spart[wid * 128 + nf * 8 + 2 * lane]     = eA;
                    spart[wid * 128 + nf * 8 + 2 * lane + 1] = eB;
                }
            }

            // ---- MMA2: O += S @ V^T ----
            const uint32_t voff = vbase + voff_l;
#pragma unroll
            for (int kc = 0; kc < 8; kc++) {
                uint32_t ahi[4], alo[4];
                ahi[0] = split2(sacc[2*kc][0],   sacc[2*kc][1],   alo[0]);
                ahi[1] = split2(sacc[2*kc][2],   sacc[2*kc][3],   alo[1]);
                ahi[2] = split2(sacc[2*kc+1][0], sacc[2*kc+1][1], alo[2]);
                ahi[3] = split2(sacc[2*kc+1][2], sacc[2*kc+1][3], alo[3]);
                const uint32_t ko = (uint32_t)(kc * 32);
#pragma unroll
                for (int p = 0; p < 4; p++) {
                    uint32_t bh[4], bl[4];
                    LDSM_X4(bh, voff + (uint32_t)(p * 16 * PVB) + ko);
                    LDSM_X4(bl, voff + VSZ + (uint32_t)(p * 16 * PVB) + ko);
                    mma16816(oacc[2*p],   ahi, bh);
                    mma16816(oacc[2*p+1], ahi, bh + 2);
                    mma16816(oacc[2*p],   ahi, bl);
                    mma16816(oacc[2*p+1], ahi, bl + 2);
                    mma16816(oacc[2*p],   alo, bh);
                    mma16816(oacc[2*p+1], alo, bh + 2);
                }
            }

            __syncthreads();
            // cross-warp column-sum -> g_part[h][sblk][t]
            if (tid < 128) {
                float s = 0.f;
#pragma unroll
                for (int w = 0; w < 8; w++) s += spart[w * 128 + tid];
                g_part[((h * 16 + sblk) << 11) + (tb << 7) + tid] = s;
            }
        }

        // ---- epilogue: Z = 0.125 * O (hi/lo split) ----
        {
            const int r0 = row0 + wid * 16 + (lane >> 2);
            const int cb2 = 2 * (lane & 3);
#pragma unroll
            for (int nf = 0; nf < 8; nf++) {
                const int col = h * HDIM + nf * 8 + cb2;
                uint32_t lp, hp;
                hp = split2(oacc[nf][0] * 0.125f, oacc[nf][1] * 0.125f, lp);
                *(uint32_t*)(g_zh + (size_t)r0 * D_MODEL + col) = hp;
                *(uint32_t*)(g_zl + (size_t)r0 * D_MODEL + col) = lp;
                hp = split2(oacc[nf][2] * 0.125f, oacc[nf][3] * 0.125f, lp);
                *(uint32_t*)(g_zh + (size_t)(r0 + 8) * D_MODEL + col) = hp;
                *(uint32_t*)(g_zl + (size_t)(r0 + 8) * D_MODEL + col) = lp;
            }
        }
        __syncthreads();
    }
}

// ---------------------------------------------------------------------------
// L[h][t] = log( t + sum_{sb>=tb} part[h][sb][t] )
// ---------------------------------------------------------------------------
__global__ __launch_bounds__(128) void lse_reduce()
{
    const int h = blockIdx.y, tb = blockIdx.x;
    const int t = (tb << 7) + threadIdx.x;
    float acc = (float)t;
    for (int sbk = tb; sbk < 16; sbk++)
        acc += g_part[((h * 16 + sbk) << 11) + t];
    g_L[h * S_LEN + t] = logf(acc);
}

// ---------------------------------------------------------------------------
// c[h][v] = sum_t L[h][t] * V[t][h*64+v]
// ---------------------------------------------------------------------------
__global__ __launch_bounds__(256) void compute_c_tc()
{
    __shared__ float part[4][HDIM];
    const int h = blockIdx.x;
    const int v = threadIdx.x & 63;
    const int g = threadIdx.x >> 6;
    const bf16* th = g_vth + (size_t)(h * HDIM + v) * S_LEN;
    const bf16* tl = g_vtl + (size_t)(h * HDIM + v) * S_LEN;
    const float* Lh = g_L + h * S_LEN;
    float sum = 0.f;
    const int t0 = g * (S_LEN / 4);
    for (int t = t0; t < t0 + S_LEN / 4; t++)
        sum = fmaf(Lh[t], __bfloat162float(th[t]) + __bfloat162float(tl[t]), sum);
    part[g][v] = sum;
    __syncthreads();
    if (g == 0)
        g_c[h * HDIM + v] = (part[0][v] + part[1][v]) + (part[2][v] + part[3][v]);
}

// ---------------------------------------------------------------------------
// b'[i] = WOb[i] - sum_j WOw[i][j] * c[j]   (folds the -c correction)
// grid(32) x 256 threads: each warp handles 4 rows.
// ---------------------------------------------------------------------------
__global__ __launch_bounds__(256) void bias_adjust(
    const float* __restrict__ WOw, const float* __restrict__ WOb)
{
    const int lane = threadIdx.x & 31, wid = threadIdx.x >> 5;
    for (int rr = 0; rr < 4; rr++) {
        const int row = (blockIdx.x * 8 + wid) * 4 + rr;
        const float* wr = WOw + (size_t)row * D_MODEL;
        float s = 0.f;
        for (int j = lane; j < D_MODEL; j += 32)
            s = fmaf(wr[j], g_c[j], s);
#pragma unroll
        for (int o = 16; o > 0; o >>= 1) s += __shfl_xor_sync(0xffffffffu, s, o);
        if (lane == 0) g_badj[row] = WOb[row] - s;
    }
}

// ---------------------------------------------------------------------------
// fp32 -> bf16 hi/lo split
// ---------------------------------------------------------------------------
__global__ __launch_bounds__(256) void split_kernel(
    const float* __restrict__ src, uint32_t* __restrict__ hi, uint32_t* __restrict__ lo, int npairs)
{
    int i = blockIdx.x * 256 + threadIdx.x;
    if (i < npairs) {
        float2 v = ((const float2*)src)[i];
        uint32_t l;
        uint32_t h = split2(v.x, v.y, l);
        hi[i] = h; lo[i] = l;
    }
}

// ---------------------------------------------------------------------------
extern "C" void kernel_launch(void* const* d_in, const int* in_sizes, int n_in,
                              void* d_out, int out_size)
{
    const float* Qin = (const float*)d_in[0];
    const float* Kin = (const float*)d_in[1];
    const float* Vin = (const float*)d_in[2];
    const float* WQw = (const float*)d_in[3];
    const float* WQb = (const float*)d_in[4];
    const float* WKw = (const float*)d_in[5];
    const float* WKb = (const float*)d_in[6];
    const float* WVw = (const float*)d_in[7];
    const float* WVb = (const float*)d_in[8];
    const float* WOw = (const float*)d_in[9];
    const float* WOb = (const float*)d_in[10];
    float* Out = (float*)d_out;

#define GETP(name, sym) void* name; cudaGetSymbolAddress(&name, sym)
    GETP(iqh, g_iqh); GETP(iql, g_iql); GETP(ikh, g_ikh); GETP(ikl, g_ikl);
    GETP(ivh, g_ivh); GETP(ivl, g_ivl);
    GETP(wqh, g_wqh); GETP(wql, g_wql); GETP(wkh, g_wkh); GETP(wkl, g_wkl);
    GETP(wvh, g_wvh); GETP(wvl, g_wvl); GETP(woh, g_woh); GETP(wol, g_wol);
    GETP(qh, g_qh);   GETP(ql, g_ql);   GETP(kh, g_kh);   GETP(kl, g_kl);
    GETP(vth, g_vth); GETP(vtl, g_vtl);
    GETP(zh, g_zh);   GETP(zl, g_zl);
    GETP(badj, g_badj);
#undef GETP

    cudaFuncSetAttribute(gemm_proj<0>, cudaFuncAttributeMaxDynamicSharedMemorySize, SMEM_PROJ);
    cudaFuncSetAttribute(gemm_proj<1>, cudaFuncAttributeMaxDynamicSharedMemorySize, SMEM_PROJ);
    cudaFuncSetAttribute(gemm_proj<2>, cudaFuncAttributeMaxDynamicSharedMemorySize, SMEM_PROJ);
    cudaFuncSetAttribute(fused_attn,   cudaFuncAttributeMaxDynamicSharedMemorySize, FATTN_SMEM);

    const int npIn = S_LEN * D_MODEL / 2;
    const int npW  = D_MODEL * D_MODEL / 2;
    dim3 blk(256);

    // 1) hi/lo splits
    split_kernel<<<npIn / 256, blk>>>(Qin, (uint32_t*)iqh, (uint32_t*)iql, npIn);
    split_kernel<<<npIn / 256, blk>>>(Kin, (uint32_t*)ikh, (uint32_t*)ikl, npIn);
    split_kernel<<<npIn / 256, blk>>>(Vin, (uint32_t*)ivh, (uint32_t*)ivl, npIn);
    split_kernel<<<npW / 256, blk>>>(WQw, (uint32_t*)wqh, (uint32_t*)wql, npW);
    split_kernel<<<npW / 256, blk>>>(WKw, (uint32_t*)wkh, (uint32_t*)wkl, npW);
    split_kernel<<<npW / 256, blk>>>(WVw, (uint32_t*)wvh, (uint32_t*)wvl, npW);
    split_kernel<<<npW / 256, blk>>>(WOw, (uint32_t*)woh, (uint32_t*)wol, npW);

    // 2) projections
    dim3 gproj(D_MODEL / 128, S_LEN / 128);
    gemm_proj<0><<<gproj, blk, SMEM_PROJ>>>((bf16*)iqh, (bf16*)iql, (bf16*)wqh, (bf16*)wql,
                                            WQb, (bf16*)qh, (bf16*)ql, nullptr);
    gemm_proj<0><<<gproj, blk, SMEM_PROJ>>>((bf16*)ikh, (bf16*)ikl, (bf16*)wkh, (bf16*)wkl,
                                            WKb, (bf16*)kh, (bf16*)kl, nullptr);
    gemm_proj<1><<<gproj, blk, SMEM_PROJ>>>((bf16*)ivh, (bf16*)ivl, (bf16*)wvh, (bf16*)wvl,
                                            WVb, (bf16*)vth, (bf16*)vtl, nullptr);

    // 3) fused attention (QK^T -> mask -> exp partials + PV), balanced pairs
    dim3 gfa(8, NHEAD);
    fused_attn<<<gfa, blk, FATTN_SMEM>>>();

    // 4) L, c, adjusted bias
    dim3 glse(16, NHEAD);
    lse_reduce<<<glse, dim3(128)>>>();
    compute_c_tc<<<NHEAD, blk>>>();
    bias_adjust<<<32, blk>>>(WOw, WOb);

    // 5) output projection with folded bias
    gemm_proj<2><<<gproj, blk, SMEM_PROJ>>>((bf16*)zh, (bf16*)zl, (bf16*)woh, (bf16*)wol,
                                            (const float*)badj, nullptr, nullptr, Out);
}